// round 16
// baseline (speedup 1.0000x reference)
#include <cuda_runtime.h>
#include <math.h>

// ---------------- problem constants ----------------
constexpr int NU = 100000, NM = 20000;
constexpr int FU = 32, FM = 128;
constexpr int H1 = 8, C1 = 16, D1 = 128;   // layer 1
constexpr int H2 = 4, C2 = 128, D2 = 512;  // layer 2
constexpr int E = 250000, EL = 200000;
constexpr int HID = 16;

// ---------------- device scratch ----------------
__device__ float g_hs1mu[(size_t)NM * D1];
__device__ float g_zu[(size_t)NU * D1];
__device__ float g_zm[(size_t)NM * D1];
__device__ float g_psu[(size_t)NU * 64];
__device__ float g_psm[(size_t)NM * 64];
__device__ float g_pu[(size_t)NU * HID];
__device__ float g_pm[(size_t)NM * HID];
__device__ float g_su1[(size_t)NU * H1];
__device__ float g_su2[(size_t)NU * H1];
__device__ float g_sm1[(size_t)NM * H1];
__device__ float g_sm2[(size_t)NM * H1];
__device__ float g_wa1[FU * H1];
__device__ float g_wa2[FU * H1];
__device__ float g_wa3[FM * H1];
__device__ float g_wa4[FM * H1];
__device__ float g_wb1[D1 * H2];
__device__ float g_wb2[D1 * H2];
__device__ float g_wb3[D1 * H2];
__device__ float g_wb4[D1 * H2];
__device__ float g_wfum[128 * 64];
__device__ float g_wfmu[128 * 64];
__device__ __align__(16) float g_bc[16];
// CSR
__device__ int g_rp_um[NM + 1];
__device__ int g_rp_mu[NU + 1];
__device__ int g_csr_um[E];
__device__ int g_csr_mu[E];
__device__ int g_cnt[NM + NU];
__device__ int g_bsum[256];

static inline int ceil_div(int a, int b) { return (a + b - 1) / b; }

// ---------------- prep sizing ----------------
constexpr int PO1 = 0,            PN1 = FU * H1;
constexpr int PO2 = PO1 + PN1,    PN2 = FU * H1;
constexpr int PO3 = PO2 + PN2,    PN3 = FM * H1;
constexpr int PO4 = PO3 + PN3,    PN4 = FM * H1;
constexpr int PO5 = PO4 + PN4,    PN5 = D1 * H2;
constexpr int PO6 = PO5 + PN5,    PN6 = D1 * H2;
constexpr int PO7 = PO6 + PN6,    PN7 = D1 * H2;
constexpr int PO8 = PO7 + PN7,    PN8 = D1 * H2;
constexpr int PO9 = PO8 + PN8,    PN9 = 128 * 64;
constexpr int PO10 = PO9 + PN9,   PN10 = 128 * 64;
constexpr int PO11 = PO10 + PN10, PN11 = 16;
constexpr int PTOT = PO11 + PN11;

// ---------------- dispatch block counts ----------------
constexpr int NB_SGEMM = (NM + 127) / 128;
constexpr int NB_HIST = (E + 255) / 256;
constexpr int NB_PREP = (PTOT + 255) / 256;
constexpr int NB_MEGA1 = NB_SGEMM + NB_HIST + NB_PREP;
constexpr int NB_SXU  = (NU + 7) / 8;
constexpr int NB_SXM  = (NM + 7) / 8;
constexpr int NB_RED  = 20 + 98;
constexpr int NB_F2R = NB_SXU + NB_SXM + NB_RED;
constexpr int NB_AG_UM = (NM + 7) / 8;
constexpr int NB_AG_MU = (NU + 7) / 8;
constexpr int NB_AGGR = NB_AG_UM + NB_AG_MU;
constexpr int NB_PROJU = (NU + 127) / 128;
constexpr int NB_PROJM = (NM + 127) / 128;
constexpr int NB_PROJ2 = NB_PROJU + NB_PROJM;

// ================= CSR scan/scatter =================
__global__ void scan2_k(int* __restrict__ bsum, int nb1, int nb2) {
    int t = threadIdx.x;
    if (t == 0) {
        int acc = 0;
        for (int i = 0; i < nb1; i++) { int v = bsum[i]; bsum[i] = acc; acc += v; }
    } else if (t == 32) {
        int acc = 0;
        for (int i = 0; i < nb2; i++) { int v = bsum[128 + i]; bsum[128 + i] = acc; acc += v; }
    }
}

__global__ void blkscan2_k(int* __restrict__ deg1, int* __restrict__ rp1, int n1, int nb1, int ne1,
                           int* __restrict__ deg2, int* __restrict__ rp2, int n2, int ne2,
                           const int* __restrict__ bsum) {
    __shared__ int ts[256];
    int gb = blockIdx.x, tid = threadIdx.x;
    int* deg; int* rp; int n, b, bo, ne;
    if (gb < nb1) { deg = deg1; rp = rp1; n = n1; b = gb; bo = 0; ne = ne1; }
    else          { deg = deg2; rp = rp2; n = n2; b = gb - nb1; bo = 128; ne = ne2; }
    int base = b * 1024 + tid * 4;
    int v[4]; int loc = 0;
#pragma unroll
    for (int j = 0; j < 4; j++) { int idx = base + j; v[j] = (idx < n) ? deg[idx] : 0; loc += v[j]; }
    ts[tid] = loc; __syncthreads();
    for (int o = 1; o < 256; o <<= 1) {
        int t = (tid >= o) ? ts[tid - o] : 0;
        __syncthreads();
        ts[tid] += t;
        __syncthreads();
    }
    int excl = ts[tid] - loc + bsum[bo + b];
#pragma unroll
    for (int j = 0; j < 4; j++) {
        int idx = base + j;
        if (idx < n) { rp[idx] = excl; deg[idx] = excl; }
        excl += v[j];
    }
    if (b == 0 && tid == 0) rp[n] = ne;
}

__global__ void scatter2_k(const int* __restrict__ s1, const int* __restrict__ d1,
                           int* __restrict__ cur1, int* __restrict__ o1,
                           const int* __restrict__ s2, const int* __restrict__ d2,
                           int* __restrict__ cur2, int* __restrict__ o2, int ne) {
    int e = blockIdx.x * blockDim.x + threadIdx.x;
    if (e >= ne) return;
    { int p = atomicAdd(&cur1[d1[e]], 1); o1[p] = s1[e]; }
    { int p = atomicAdd(&cur2[d2[e]], 1); o2[p] = s2[e]; }
}

// ================= fold helpers =================
__device__ __forceinline__ float fold_elem(const float* __restrict__ W,
                                           const float* __restrict__ a,
                                           int H, int C, int t) {
    int k = t / H, h = t - k * H;
    const float* wr = W + (size_t)k * H * C + h * C;
    const float* ar = a + h * C;
    float s = 0.f;
    for (int c = 0; c < C; c++) s += wr[c] * ar[c];
    return s;
}
__device__ __forceinline__ float fold_dec_elem(const float* __restrict__ Ws,
                                               const float* __restrict__ dw1,
                                               int dec_off, int t) {
    int k = t >> 6, hj = t & 63;
    int h = hj >> 4, j = hj & 15;
    const float* wrow = Ws + (size_t)k * 512 + h * 128;
    const float* drow = dw1 + (size_t)(dec_off + h * 128) * 16 + j;
    float s = 0.f;
    for (int c = 0; c < 128; c++) s += wrow[c] * drow[c * 16];
    return s;
}

// ================= sgemm device fn =================
__device__ void dev_sgemm(const float* __restrict__ A, int lda,
                          const float* __restrict__ B, int ldb,
                          float* __restrict__ C, int ldc, int M, int K,
                          int bid, float* sh) {
    float* As = sh;
    float* Bs = sh + 1024;
    int t  = threadIdx.x;
    int tx = t & 15, ty = t >> 4;
    int row0 = bid * 128;
    float acc[8][8] = {};
    for (int k0 = 0; k0 < K; k0 += 8) {
        {
            int m = t >> 1, k4 = (t & 1) * 4;
            int r = row0 + m;
            float4 v = make_float4(0.f, 0.f, 0.f, 0.f);
            if (r < M) v = *(const float4*)&A[(size_t)r * lda + k0 + k4];
            As[(k4 + 0) * 128 + m] = v.x; As[(k4 + 1) * 128 + m] = v.y;
            As[(k4 + 2) * 128 + m] = v.z; As[(k4 + 3) * 128 + m] = v.w;
        }
        {
            int kk = t >> 5, n4 = (t & 31) * 4;
            *(float4*)&Bs[kk * 128 + n4] = *(const float4*)&B[(size_t)(k0 + kk) * ldb + n4];
        }
        __syncthreads();
#pragma unroll
        for (int kk = 0; kk < 8; kk++) {
            float a_[8], b_[8];
            *(float4*)&a_[0] = *(const float4*)&As[kk * 128 + ty * 8];
            *(float4*)&a_[4] = *(const float4*)&As[kk * 128 + ty * 8 + 4];
            *(float4*)&b_[0] = *(const float4*)&Bs[kk * 128 + tx * 8];
            *(float4*)&b_[4] = *(const float4*)&Bs[kk * 128 + tx * 8 + 4];
#pragma unroll
            for (int i = 0; i < 8; i++)
#pragma unroll
                for (int j = 0; j < 8; j++) acc[i][j] += a_[i] * b_[j];
        }
        __syncthreads();
    }
    for (int i = 0; i < 8; i++) {
        int r = row0 + ty * 8 + i;
        if (r >= M) break;
#pragma unroll
        for (int j4 = 0; j4 < 8; j4 += 4) {
            float4 v = make_float4(acc[i][j4], acc[i][j4 + 1], acc[i][j4 + 2], acc[i][j4 + 3]);
            *(float4*)&C[(size_t)r * ldc + tx * 8 + j4] = v;
        }
    }
}

// ================= mega1: sgemm | hist | folds =================
__global__ void __launch_bounds__(256) mega1_k(
    const float* xm, const float* w1mu_s, float* hs1mu,
    const int* um_dst, const int* mu_dst, int* cnt_um, int* cnt_mu,
    const float* w1um_s, const float* a1um_s, const float* w1mu_d, const float* a1mu_d,
    const float* w1um_d, const float* a1um_d, const float* a1mu_s,
    const float* w2um_s, const float* a2um_s, const float* w2mu_d, const float* a2mu_d,
    const float* w2um_d, const float* a2um_d, const float* w2mu_s, const float* a2mu_s,
    const float* dw1, const float* db1, const float* b2um, const float* b2mu,
    float* wa1, float* wa2, float* wa3, float* wa4,
    float* wb1, float* wb2, float* wb3, float* wb4,
    float* wfum, float* wfmu, float* bc) {
    __shared__ float sh[2048];
    int gb = blockIdx.x;
    if (gb < NB_SGEMM) {
        dev_sgemm(xm, FM, w1mu_s, D1, hs1mu, D1, NM, FM, gb, sh);
    } else if (gb < NB_SGEMM + NB_HIST) {
        int e = (gb - NB_SGEMM) * 256 + threadIdx.x;
        if (e < E) {
            atomicAdd(&cnt_um[um_dst[e]], 1);
            atomicAdd(&cnt_mu[mu_dst[e]], 1);
        }
    } else {
        int t = (gb - NB_SGEMM - NB_HIST) * 256 + threadIdx.x;
        if (t >= PTOT) return;
        if (t < PO2)       wa1[t - PO1] = fold_elem(w1um_s, a1um_s, H1, C1, t - PO1);
        else if (t < PO3)  wa2[t - PO2] = fold_elem(w1mu_d, a1mu_d, H1, C1, t - PO2);
        else if (t < PO4)  wa3[t - PO3] = fold_elem(w1um_d, a1um_d, H1, C1, t - PO3);
        else if (t < PO5)  wa4[t - PO4] = fold_elem(w1mu_s, a1mu_s, H1, C1, t - PO4);
        else if (t < PO6)  wb1[t - PO5] = fold_elem(w2um_s, a2um_s, H2, C2, t - PO5);
        else if (t < PO7)  wb2[t - PO6] = fold_elem(w2mu_d, a2mu_d, H2, C2, t - PO6);
        else if (t < PO8)  wb3[t - PO7] = fold_elem(w2um_d, a2um_d, H2, C2, t - PO7);
        else if (t < PO9)  wb4[t - PO8] = fold_elem(w2mu_s, a2mu_s, H2, C2, t - PO8);
        else if (t < PO10) wfum[t - PO9]  = fold_dec_elem(w2um_s, dw1, 512, t - PO9);
        else if (t < PO11) wfmu[t - PO10] = fold_dec_elem(w2mu_s, dw1, 0,   t - PO10);
        else {
            int j = t - PO11;
            float s = db1[j];
            for (int d = 0; d < 512; d++)
                s += b2mu[d] * dw1[d * 16 + j] + b2um[d] * dw1[(512 + d) * 16 + j];
            bc[j] = s;
        }
    }
}

// ================= scores device fn =================
template <int K>
__device__ void dev_scores2(const float* __restrict__ x,
                            const float* __restrict__ wa1, const float* __restrict__ wa2,
                            float* __restrict__ y1, float* __restrict__ y2, int n,
                            int bid, float* sh) {
    constexpr int H = 8;
    float* s1 = sh;
    float* s2 = sh + K * H;
    int t = threadIdx.x;
    for (int i = t; i < K * H; i += 256) { s1[i] = wa1[i]; s2[i] = wa2[i]; }
    __syncthreads();
    int warp = t >> 5, lane = t & 31;
    int node = bid * 8 + warp;
    if (node >= n) return;
    const float* row = x + (size_t)node * K;
    float a1[H] = {}, a2[H] = {};
#pragma unroll
    for (int k0 = 0; k0 < K; k0 += 32) {
        float xv = row[k0 + lane];
#pragma unroll
        for (int h = 0; h < H; h++) {
            a1[h] += xv * s1[(k0 + lane) * H + h];
            a2[h] += xv * s2[(k0 + lane) * H + h];
        }
    }
#pragma unroll
    for (int h = 0; h < H; h++) {
#pragma unroll
        for (int o = 16; o; o >>= 1) {
            a1[h] += __shfl_xor_sync(0xffffffffu, a1[h], o);
            a2[h] += __shfl_xor_sync(0xffffffffu, a2[h], o);
        }
    }
    if (lane == 0) {
#pragma unroll
        for (int h = 0; h < H; h++) {
            y1[(size_t)node * H + h] = a1[h];
            y2[(size_t)node * H + h] = a2[h];
        }
    }
}

// ================= front2r: scores(xu) | scores(xm) | reduce2 =================
__global__ void __launch_bounds__(256) front2r_k(
    const float* xu, const float* xm,
    const float* wa1, const float* wa2, const float* wa3, const float* wa4,
    float* su1, float* su2, float* sm1, float* sm2,
    const int* cnt, int* bsum, int nb_um) {
    __shared__ float sh[2048];
    int gb = blockIdx.x;
    if (gb < NB_SXU) {
        dev_scores2<FU>(xu, wa1, wa2, su1, su2, NU, gb, sh);
    } else if (gb < NB_SXU + NB_SXM) {
        dev_scores2<FM>(xm, wa3, wa4, sm1, sm2, NM, gb - NB_SXU, sh);
    } else {
        int* shi = (int*)sh;
        int rb = gb - NB_SXU - NB_SXM;
        const int* deg; int n, b, bo;
        if (rb < nb_um) { deg = cnt; n = NM; b = rb; bo = 0; }
        else            { deg = cnt + NM; n = NU; b = rb - nb_um; bo = 128; }
        int tid = threadIdx.x;
        int base = b * 1024;
        int s = 0;
        for (int i = tid; i < 1024; i += 256) {
            int idx = base + i;
            if (idx < n) s += deg[idx];
        }
        shi[tid] = s; __syncthreads();
        for (int o = 128; o; o >>= 1) { if (tid < o) shi[tid] += shi[tid + o]; __syncthreads(); }
        if (tid == 0) bsum[bo + b] = shi[0];
    }
}

// ================= layer-1 aggregations (um fused with l1post) =================
__device__ void dev_aggr_um_fused(const int* __restrict__ rowptr, const int* __restrict__ csr,
                                  const float* __restrict__ es, const float* __restrict__ ed,
                                  const float* __restrict__ xu,
                                  float* __restrict__ zm, int nd, int bid, float* sh) {
    float* Wsh = sh;           // 32*128
    float* bsh = sh + 4096;    // 128
    float* vsh = sh + 4224;    // 8 warps * 264
    int warp = threadIdx.x >> 5;
    int lane = threadIdx.x & 31;
    int w = bid * 8 + warp;
    if (w >= nd) return;
    int rs = rowptr[w], re = rowptr[w + 1];
    float edv[8], m[8], ssum[8], acc[8];
    {
        float4 e0 = *(const float4*)&ed[(size_t)w * 8];
        float4 e1 = *(const float4*)&ed[(size_t)w * 8 + 4];
        edv[0]=e0.x; edv[1]=e0.y; edv[2]=e0.z; edv[3]=e0.w;
        edv[4]=e1.x; edv[5]=e1.y; edv[6]=e1.z; edv[7]=e1.w;
    }
#pragma unroll
    for (int h = 0; h < 8; h++) { m[h] = -INFINITY; ssum[h] = 0.f; acc[h] = 0.f; }
    for (int i = rs + lane; i < re; i += 32) {
        int s = csr[i];
        float4 v0 = *(const float4*)&es[(size_t)s * 8];
        float4 v1 = *(const float4*)&es[(size_t)s * 8 + 4];
        float ev[8] = { v0.x, v0.y, v0.z, v0.w, v1.x, v1.y, v1.z, v1.w };
#pragma unroll
        for (int h = 0; h < 8; h++) {
            float e = ev[h] + edv[h];
            e = e > 0.f ? e : 0.2f * e;
            m[h] = fmaxf(m[h], e);
        }
    }
#pragma unroll
    for (int h = 0; h < 8; h++)
#pragma unroll
        for (int o = 16; o; o >>= 1) m[h] = fmaxf(m[h], __shfl_xor_sync(0xffffffffu, m[h], o));
    int i = rs;
    for (; i + 1 < re; i += 2) {
        int s0 = csr[i], s1 = csr[i + 1];
        float x0 = xu[(size_t)s0 * 32 + lane];
        float x1 = xu[(size_t)s1 * 32 + lane];
        float4 a0 = *(const float4*)&es[(size_t)s0 * 8];
        float4 a1 = *(const float4*)&es[(size_t)s0 * 8 + 4];
        float4 b0 = *(const float4*)&es[(size_t)s1 * 8];
        float4 b1 = *(const float4*)&es[(size_t)s1 * 8 + 4];
        float e0[8] = { a0.x, a0.y, a0.z, a0.w, a1.x, a1.y, a1.z, a1.w };
        float e1[8] = { b0.x, b0.y, b0.z, b0.w, b1.x, b1.y, b1.z, b1.w };
#pragma unroll
        for (int h = 0; h < 8; h++) {
            float u = e0[h] + edv[h]; u = u > 0.f ? u : 0.2f * u;
            float v = e1[h] + edv[h]; v = v > 0.f ? v : 0.2f * v;
            float au = __expf(u - m[h]);
            float av = __expf(v - m[h]);
            ssum[h] += au + av;
            acc[h] += au * x0 + av * x1;
        }
    }
    if (i < re) {
        int s = csr[i];
        float xv = xu[(size_t)s * 32 + lane];
        float4 v0 = *(const float4*)&es[(size_t)s * 8];
        float4 v1 = *(const float4*)&es[(size_t)s * 8 + 4];
        float ev[8] = { v0.x, v0.y, v0.z, v0.w, v1.x, v1.y, v1.z, v1.w };
#pragma unroll
        for (int h = 0; h < 8; h++) {
            float e = ev[h] + edv[h];
            e = e > 0.f ? e : 0.2f * e;
            float a = __expf(e - m[h]);
            ssum[h] += a;
            acc[h] += a * xv;
        }
    }
    float* vw = vsh + warp * 264;
#pragma unroll
    for (int h = 0; h < 8; h++)
        vw[h * 33 + lane] = acc[h] * (1.f / (ssum[h] + 1e-16f));
    __syncwarp();
    const float* arow = vw + (lane >> 2) * 33;
    float4 o = *(const float4*)&bsh[lane * 4];
#pragma unroll
    for (int k = 0; k < 32; k++) {
        float av = arow[k];
        float4 wv = *(const float4*)&Wsh[k * 128 + lane * 4];
        o.x += av * wv.x; o.y += av * wv.y;
        o.z += av * wv.z; o.w += av * wv.w;
    }
    o.x = fmaxf(o.x, 0.f); o.y = fmaxf(o.y, 0.f);
    o.z = fmaxf(o.z, 0.f); o.w = fmaxf(o.w, 0.f);
    *(float4*)&zm[(size_t)w * 128 + lane * 4] = o;
}

__device__ void dev_aggr_l1mu(const int* __restrict__ rowptr, const int* __restrict__ csr,
                              const float* __restrict__ es, const float* __restrict__ ed,
                              const float* __restrict__ feat, const float* __restrict__ bias,
                              float* __restrict__ out, int nd, int bid) {
    int w = bid * 8 + (threadIdx.x >> 5);
    int lane = threadIdx.x & 31;
    if (w >= nd) return;
    int rs = rowptr[w], re = rowptr[w + 1];
    float edv[8], m[8];
    {
        float4 e0 = *(const float4*)&ed[(size_t)w * 8];
        float4 e1 = *(const float4*)&ed[(size_t)w * 8 + 4];
        edv[0]=e0.x; edv[1]=e0.y; edv[2]=e0.z; edv[3]=e0.w;
        edv[4]=e1.x; edv[5]=e1.y; edv[6]=e1.z; edv[7]=e1.w;
    }
#pragma unroll
    for (int h = 0; h < 8; h++) m[h] = -INFINITY;
    for (int i = rs + lane; i < re; i += 32) {
        int s = csr[i];
        float4 v0 = *(const float4*)&es[(size_t)s * 8];
        float4 v1 = *(const float4*)&es[(size_t)s * 8 + 4];
        float ev[8] = { v0.x, v0.y, v0.z, v0.w, v1.x, v1.y, v1.z, v1.w };
#pragma unroll
        for (int h = 0; h < 8; h++) {
            float e = ev[h] + edv[h];
            e = e > 0.f ? e : 0.2f * e;
            m[h] = fmaxf(m[h], e);
        }
    }
#pragma unroll
    for (int h = 0; h < 8; h++)
#pragma unroll
        for (int o = 16; o; o >>= 1) m[h] = fmaxf(m[h], __shfl_xor_sync(0xffffffffu, m[h], o));
    int hh = lane >> 2;
    float edh = edv[hh], mh = m[hh];
    float ssum = 0.f;
    float4 acc = make_float4(0.f, 0.f, 0.f, 0.f);
    int i = rs;
    for (; i + 1 < re; i += 2) {
        int s0 = csr[i], s1 = csr[i + 1];
        float e0 = es[(size_t)s0 * 8 + hh] + edh;
        float e1 = es[(size_t)s1 * 8 + hh] + edh;
        float4 x0 = *(const float4*)&feat[(size_t)s0 * 128 + lane * 4];
        float4 x1 = *(const float4*)&feat[(size_t)s1 * 128 + lane * 4];
        e0 = e0 > 0.f ? e0 : 0.2f * e0;
        e1 = e1 > 0.f ? e1 : 0.2f * e1;
        float a0 = __expf(e0 - mh);
        float a1 = __expf(e1 - mh);
        ssum += a0 + a1;
        acc.x += a0 * x0.x + a1 * x1.x; acc.y += a0 * x0.y + a1 * x1.y;
        acc.z += a0 * x0.z + a1 * x1.z; acc.w += a0 * x0.w + a1 * x1.w;
    }
    if (i < re) {
        int s = csr[i];
        float e = es[(size_t)s * 8 + hh] + edh;
        e = e > 0.f ? e : 0.2f * e;
        float a = __expf(e - mh);
        ssum += a;
        float4 x = *(const float4*)&feat[(size_t)s * 128 + lane * 4];
        acc.x += a * x.x; acc.y += a * x.y;
        acc.z += a * x.z; acc.w += a * x.w;
    }
    float sinv = 1.f / (ssum + 1e-16f);
    float4 bb = *(const float4*)&bias[lane * 4];
    float4 o = make_float4(fmaxf(acc.x * sinv + bb.x, 0.f), fmaxf(acc.y * sinv + bb.y, 0.f),
                           fmaxf(acc.z * sinv + bb.z, 0.f), fmaxf(acc.w * sinv + bb.w, 0.f));
    *(float4*)&out[(size_t)w * 128 + lane * 4] = o;
}

__global__ void __launch_bounds__(256) fused_aggr1_k(
    const int* rp_um, const int* csr_um, const float* su1, const float* sm1,
    const float* xu, const float* w1um_s, const float* b1um, float* zm,
    const int* rp_mu, const int* csr_mu, const float* sm2, const float* su2,
    const float* hs1mu, const float* b1mu, float* zu) {
    __shared__ float sh[6336];
    int gb = blockIdx.x;
    if (gb < NB_AG_UM) {
        for (int i = threadIdx.x; i < 1024; i += 256)
            ((float4*)sh)[i] = ((const float4*)w1um_s)[i];
        if (threadIdx.x < 32) ((float4*)(sh + 4096))[threadIdx.x] = ((const float4*)b1um)[threadIdx.x];
        __syncthreads();
        dev_aggr_um_fused(rp_um, csr_um, su1, sm1, xu, zm, NM, gb, sh);
    } else {
        dev_aggr_l1mu(rp_mu, csr_mu, sm2, su2, hs1mu, b1mu, zu, NU, gb - NB_AG_UM);
    }
}

// ================= proj64 + scores (merged zu | zm) =================
__device__ void dev_proj64s(const float* __restrict__ X, const float* __restrict__ Wf,
                            const float* __restrict__ wbA, const float* __restrict__ wbB,
                            float* __restrict__ Y, float* __restrict__ y1, float* __restrict__ y2,
                            int M, int bid, float* sh) {
    float* As = sh;            // 16*132
    float* Bs = sh + 2112;     // 16*64
    float* Wb = sh + 3136;     // 128*8
    int t = threadIdx.x;
    for (int i = t; i < 128 * 4; i += 256) {
        Wb[(i >> 2) * 8 + (i & 3)]     = wbA[i];
        Wb[(i >> 2) * 8 + 4 + (i & 3)] = wbB[i];
    }
    int tx = t & 15, ty = t >> 4;
    int row0 = bid * 128;
    float acc[8][4] = {};
    float accs[8] = {};
    for (int k0 = 0; k0 < 128; k0 += 16) {
#pragma unroll
        for (int l = 0; l < 2; l++) {
            int i = t * 2 + l;
            int row = i >> 2, k4 = (i & 3) * 4;
            int r = row0 + row;
            float4 v = make_float4(0.f, 0.f, 0.f, 0.f);
            if (r < M) v = *(const float4*)&X[(size_t)r * 128 + k0 + k4];
            As[(k4 + 0) * 132 + row] = v.x; As[(k4 + 1) * 132 + row] = v.y;
            As[(k4 + 2) * 132 + row] = v.z; As[(k4 + 3) * 132 + row] = v.w;
        }
        {
            int kk = t >> 4, c4 = (t & 15) * 4;
            *(float4*)&Bs[kk * 64 + c4] = *(const float4*)&Wf[(size_t)(k0 + kk) * 64 + c4];
        }
        __syncthreads();
#pragma unroll
        for (int kk = 0; kk < 16; kk++) {
            float a_[8], b_[4];
            *(float4*)&a_[0] = *(const float4*)&As[kk * 132 + ty * 8];
            *(float4*)&a_[4] = *(const float4*)&As[kk * 132 + ty * 8 + 4];
            *(float4*)&b_[0] = *(const float4*)&Bs[kk * 64 + tx * 4];
#pragma unroll
            for (int i = 0; i < 8; i++)
#pragma unroll
                for (int j = 0; j < 4; j++) acc[i][j] += a_[i] * b_[j];
            if (tx < 8) {
                float bsv = Wb[(k0 + kk) * 8 + tx];
#pragma unroll
                for (int i = 0; i < 8; i++) accs[i] += a_[i] * bsv;
            }
        }
        __syncthreads();
    }
    for (int i = 0; i < 8; i++) {
        int r = row0 + ty * 8 + i;
        if (r >= M) break;
        *(float4*)&Y[(size_t)r * 64 + tx * 4] =
            make_float4(acc[i][0], acc[i][1], acc[i][2], acc[i][3]);
        if (tx < 4)       y1[(size_t)r * 4 + tx] = accs[i];
        else if (tx < 8)  y2[(size_t)r * 4 + tx - 4] = accs[i];
    }
}

__global__ void __launch_bounds__(256) proj2_k(
    const float* zu, const float* wfum, const float* wb1, const float* wb2,
    float* psu, float* su1, float* su2,
    const float* zm, const float* wfmu, const float* wb3, const float* wb4,
    float* psm, float* sm1, float* sm2) {
    __shared__ float sh[4224];
    int gb = blockIdx.x;
    if (gb < NB_PROJU)
        dev_proj64s(zu, wfum, wb1, wb2, psu, su1, su2, NU, gb, sh);
    else
        dev_proj64s(zm, wfmu, wb3, wb4, psm, sm1, sm2, NM, gb - NB_PROJU, sh);
}

// ================= layer-2 aggregation (merged um+mu), MLP=4 =================
__device__ void dev_aggr16(const int* __restrict__ rowptr, const int* __restrict__ csr,
                           const float* __restrict__ es, const float* __restrict__ ed,
                           const float* __restrict__ ps, float* __restrict__ out,
                           int nd, int bid) {
    int w = bid * 8 + (threadIdx.x >> 5);
    int lane = threadIdx.x & 31;
    if (w >= nd) return;
    int rs = rowptr[w], re = rowptr[w + 1];
    float edv[4], m[4];
    {
        float4 e0 = *(const float4*)&ed[(size_t)w * 4];
        edv[0]=e0.x; edv[1]=e0.y; edv[2]=e0.z; edv[3]=e0.w;
    }
#pragma unroll
    for (int h = 0; h < 4; h++) m[h] = -INFINITY;
    for (int i = rs + lane; i < re; i += 32) {
        int s = csr[i];
        float4 ev = *(const float4*)&es[(size_t)s * 4];
        float e4[4] = { ev.x, ev.y, ev.z, ev.w };
#pragma unroll
        for (int h = 0; h < 4; h++) {
            float e = e4[h] + edv[h];
            e = e > 0.f ? e : 0.2f * e;
            m[h] = fmaxf(m[h], e);
        }
    }
#pragma unroll
    for (int h = 0; h < 4; h++)
#pragma unroll
        for (int o = 16; o; o >>= 1) m[h] = fmaxf(m[h], __shfl_xor_sync(0xffffffffu, m[h], o));
    int hh = lane >> 3;
    float edh = edv[hh], mh = m[hh];
    float ssum = 0.f, ax = 0.f, ay = 0.f;
    int i = rs;
    // MLP=4: 4 independent csr+score+feature gathers in flight
    for (; i + 3 < re; i += 4) {
        int s0 = csr[i], s1 = csr[i + 1], s2 = csr[i + 2], s3 = csr[i + 3];
        float e0 = es[(size_t)s0 * 4 + hh] + edh;
        float e1 = es[(size_t)s1 * 4 + hh] + edh;
        float e2 = es[(size_t)s2 * 4 + hh] + edh;
        float e3 = es[(size_t)s3 * 4 + hh] + edh;
        float2 v0 = *(const float2*)&ps[(size_t)s0 * 64 + lane * 2];
        float2 v1 = *(const float2*)&ps[(size_t)s1 * 64 + lane * 2];
        float2 v2 = *(const float2*)&ps[(size_t)s2 * 64 + lane * 2];
        float2 v3 = *(const float2*)&ps[(size_t)s3 * 64 + lane * 2];
        e0 = e0 > 0.f ? e0 : 0.2f * e0;
        e1 = e1 > 0.f ? e1 : 0.2f * e1;
        e2 = e2 > 0.f ? e2 : 0.2f * e2;
        e3 = e3 > 0.f ? e3 : 0.2f * e3;
        float a0 = __expf(e0 - mh), a1 = __expf(e1 - mh);
        float a2 = __expf(e2 - mh), a3 = __expf(e3 - mh);
        ssum += (a0 + a1) + (a2 + a3);
        ax += a0 * v0.x + a1 * v1.x + a2 * v2.x + a3 * v3.x;
        ay += a0 * v0.y + a1 * v1.y + a2 * v2.y + a3 * v3.y;
    }
    for (; i < re; i++) {
        int s = csr[i];
        float e = es[(size_t)s * 4 + hh] + edh;
        e = e > 0.f ? e : 0.2f * e;
        float a = __expf(e - mh);
        ssum += a;
        float2 v = *(const float2*)&ps[(size_t)s * 64 + lane * 2];
        ax += a * v.x; ay += a * v.y;
    }
    float sinv = 1.f / (ssum + 1e-16f);
    ax *= sinv; ay *= sinv;
    ax += __shfl_xor_sync(0xffffffffu, ax, 8);
    ay += __shfl_xor_sync(0xffffffffu, ay, 8);
    ax += __shfl_xor_sync(0xffffffffu, ax, 16);
    ay += __shfl_xor_sync(0xffffffffu, ay, 16);
    if (lane < 8) *(float2*)&out[(size_t)w * 16 + lane * 2] = make_float2(ax, ay);
}

__global__ void __launch_bounds__(256) fused_aggr2_k(
    const int* rp_um, const int* csr_um, const float* su1, const float* sm1,
    const float* psu, float* pm,
    const int* rp_mu, const int* csr_mu, const float* sm2, const float* su2,
    const float* psm, float* pu) {
    int gb = blockIdx.x;
    if (gb < NB_AG_UM)
        dev_aggr16(rp_um, csr_um, su1, sm1, psu, pm, NM, gb);
    else
        dev_aggr16(rp_mu, csr_mu, sm2, su2, psm, pu, NU, gb - NB_AG_UM);
}

// ================= decoder =================
__global__ void dec_edge_k(const float* __restrict__ pu, const float* __restrict__ pm,
                           const int* __restrict__ lu, const int* __restrict__ lm,
                           const float* __restrict__ bc, const float* __restrict__ dw2,
                           const float* __restrict__ db2, float* __restrict__ out, int M) {
    int e = blockIdx.x * blockDim.x + threadIdx.x;
    if (e >= M) return;
    const float4* a = (const float4*)&pu[(size_t)lu[e] * 16];
    const float4* b = (const float4*)&pm[(size_t)lm[e] * 16];
    float acc = db2[0];
#pragma unroll
    for (int q = 0; q < 4; q++) {
        float4 av = a[q], bv = b[q];
        float4 dv = ((const float4*)bc)[q], wv = ((const float4*)dw2)[q];
        acc += fmaxf(av.x + bv.x + dv.x, 0.f) * wv.x;
        acc += fmaxf(av.y + bv.y + dv.y, 0.f) * wv.y;
        acc += fmaxf(av.z + bv.z + dv.z, 0.f) * wv.z;
        acc += fmaxf(av.w + bv.w + dv.w, 0.f) * wv.w;
    }
    out[e] = acc;
}

// ---------------- launch --------------------------------------------------------
extern "C" void kernel_launch(void* const* d_in, const int* in_sizes, int n_in,
                              void* d_out, int out_size) {
    const float* xu     = (const float*)d_in[0];
    const float* xm     = (const float*)d_in[1];
    const int*   um_src = (const int*)d_in[2];
    const int*   um_dst = (const int*)d_in[3];
    const int*   mu_src = (const int*)d_in[4];
    const int*   mu_dst = (const int*)d_in[5];
    const int*   lab_u  = (const int*)d_in[6];
    const int*   lab_m  = (const int*)d_in[7];
    const float* w1um_s = (const float*)d_in[8];
    const float* w1um_d = (const float*)d_in[9];
    const float* a1um_s = (const float*)d_in[10];
    const float* a1um_d = (const float*)d_in[11];
    const float* b1um   = (const float*)d_in[12];
    const float* w1mu_s = (const float*)d_in[13];
    const float* w1mu_d = (const float*)d_in[14];
    const float* a1mu_s = (const float*)d_in[15];
    const float* a1mu_d = (const float*)d_in[16];
    const float* b1mu   = (const float*)d_in[17];
    const float* w2um_s = (const float*)d_in[18];
    const float* w2um_d = (const float*)d_in[19];
    const float* a2um_s = (const float*)d_in[20];
    const float* a2um_d = (const float*)d_in[21];
    const float* b2um   = (const float*)d_in[22];
    const float* w2mu_s = (const float*)d_in[23];
    const float* w2mu_d = (const float*)d_in[24];
    const float* a2mu_s = (const float*)d_in[25];
    const float* a2mu_d = (const float*)d_in[26];
    const float* b2mu   = (const float*)d_in[27];
    const float* dw1    = (const float*)d_in[28];
    const float* db1    = (const float*)d_in[29];
    const float* dw2    = (const float*)d_in[30];
    const float* db2    = (const float*)d_in[31];
    float* out = (float*)d_out;

    float *hs1mu, *zu, *zm, *psu, *psm, *pu, *pm;
    float *su1, *su2, *sm1, *sm2;
    float *wa1, *wa2, *wa3, *wa4, *wb1, *wb2, *wb3, *wb4, *wfum, *wfmu, *bc;
    int *rp_um, *rp_mu, *csr_um, *csr_mu, *cnt, *bsum;
    cudaGetSymbolAddress((void**)&hs1mu, g_hs1mu);
    cudaGetSymbolAddress((void**)&zu,  g_zu);
    cudaGetSymbolAddress((void**)&zm,  g_zm);
    cudaGetSymbolAddress((void**)&psu, g_psu);
    cudaGetSymbolAddress((void**)&psm, g_psm);
    cudaGetSymbolAddress((void**)&pu,  g_pu);
    cudaGetSymbolAddress((void**)&pm,  g_pm);
    cudaGetSymbolAddress((void**)&su1, g_su1);
    cudaGetSymbolAddress((void**)&su2, g_su2);
    cudaGetSymbolAddress((void**)&sm1, g_sm1);
    cudaGetSymbolAddress((void**)&sm2, g_sm2);
    cudaGetSymbolAddress((void**)&wa1, g_wa1);
    cudaGetSymbolAddress((void**)&wa2, g_wa2);
    cudaGetSymbolAddress((void**)&wa3, g_wa3);
    cudaGetSymbolAddress((void**)&wa4, g_wa4);
    cudaGetSymbolAddress((void**)&wb1, g_wb1);
    cudaGetSymbolAddress((void**)&wb2, g_wb2);
    cudaGetSymbolAddress((void**)&wb3, g_wb3);
    cudaGetSymbolAddress((void**)&wb4, g_wb4);
    cudaGetSymbolAddress((void**)&wfum, g_wfum);
    cudaGetSymbolAddress((void**)&wfmu, g_wfmu);
    cudaGetSymbolAddress((void**)&bc,  g_bc);
    cudaGetSymbolAddress((void**)&rp_um, g_rp_um);
    cudaGetSymbolAddress((void**)&rp_mu, g_rp_mu);
    cudaGetSymbolAddress((void**)&csr_um, g_csr_um);
    cudaGetSymbolAddress((void**)&csr_mu, g_csr_mu);
    cudaGetSymbolAddress((void**)&cnt, g_cnt);
    cudaGetSymbolAddress((void**)&bsum, g_bsum);
    int* cnt_um = cnt;
    int* cnt_mu = cnt + NM;

    const int TB = 256;
    const int nb_um = ceil_div(NM, 1024), nb_mu = ceil_div(NU, 1024);

    // 1: zero degree counters
    cudaMemsetAsync(cnt, 0, (NM + NU) * sizeof(int));
    // 2: mega1 = sgemm(hs1mu) | histogram | all weight folds
    mega1_k<<<NB_MEGA1, 256>>>(xm, w1mu_s, hs1mu,
                               um_dst, mu_dst, cnt_um, cnt_mu,
                               w1um_s, a1um_s, w1mu_d, a1mu_d,
                               w1um_d, a1um_d, a1mu_s,
                               w2um_s, a2um_s, w2mu_d, a2mu_d,
                               w2um_d, a2um_d, w2mu_s, a2mu_s,
                               dw1, db1, b2um, b2mu,
                               wa1, wa2, wa3, wa4, wb1, wb2, wb3, wb4,
                               wfum, wfmu, bc);
    // 3: front2r = scores(xu) | scores(xm) | degree block-reduce
    front2r_k<<<NB_F2R, 256>>>(xu, xm, wa1, wa2, wa3, wa4,
                               su1, su2, sm1, sm2, cnt, bsum, nb_um);
    // 4-6: CSR scan + scatter
    scan2_k<<<1, 64>>>(bsum, nb_um, nb_mu);
    blkscan2_k<<<nb_um + nb_mu, 256>>>(cnt_um, rp_um, NM, nb_um, E, cnt_mu, rp_mu, NU, E, bsum);
    scatter2_k<<<ceil_div(E, TB), TB>>>(um_src, um_dst, cnt_um, csr_um,
                                        mu_src, mu_dst, cnt_mu, csr_mu, E);
    // 7: layer-1 aggregations (um aggregate+post fused -> zm | mu fused -> zu)
    fused_aggr1_k<<<NB_AGGR, 256>>>(rp_um, csr_um, su1, sm1, xu, w1um_s, b1um, zm,
                                    rp_mu, csr_mu, sm2, su2, hs1mu, b1mu, zu);
    // 8: proj64+scores for zu | zm
    proj2_k<<<NB_PROJ2, 256>>>(zu, wfum, wb1, wb2, psu, su1, su2,
                               zm, wfmu, wb3, wb4, psm, sm1, sm2);
    // 9: layer-2 aggregations (um | mu)
    fused_aggr2_k<<<NB_AGGR, 256>>>(rp_um, csr_um, su1, sm1, psu, pm,
                                    rp_mu, csr_mu, sm2, su2, psm, pu);
    // 10: decoder
    dec_edge_k<<<ceil_div(EL, TB), TB>>>(pu, pm, lab_u, lab_m, bc, dw2, db2, out, EL);
}